// round 5
// baseline (speedup 1.0000x reference)
#include <cuda_runtime.h>
#include <cstdint>

#define N_EDGES 3200000
#define N_NODES 100000
#define TPB 256
#define EPT 2
#define EPB (TPB * EPT)   // 512 edges per block

// 16B-aligned padded copy of pos: one LDG.128 per gather instead of 3 LDG.32.
__device__ float4 g_pos_pad[N_NODES];

__global__ __launch_bounds__(256)
void pos_pad_kernel(const float* __restrict__ pos)
{
    const int i = blockIdx.x * blockDim.x + threadIdx.x;
    if (i < N_NODES) {
        g_pos_pad[i] = make_float4(pos[i * 3 + 0], pos[i * 3 + 1], pos[i * 3 + 2], 0.0f);
    }
}

__global__ __launch_bounds__(256)
void sh_edge_attrs_kernel(const void* __restrict__ edge_index_raw,
                          const float* __restrict__ shift,
                          float* __restrict__ out)
{
    __shared__ float s_shvec[EPB * 3];   // 6144 B: shift in, vec out (per-thread in-place)
    __shared__ float s_len[EPB];         // 2048 B
    __shared__ float s_sh[EPB * 9];      // 18432 B

    const int t = threadIdx.x;
    const long long blk_base = (long long)blockIdx.x * EPB;

    // ---- stage shift slice: 384 float4 coalesced ----
    {
        const float4* gshift = (const float4*)(shift + blk_base * 3);
        float4* sdst = (float4*)s_shvec;
        sdst[t] = gshift[t];
        if (t < (EPB * 3) / 4 - TPB) sdst[t + TPB] = gshift[t + TPB];
    }

    // ---- edge indices (dtype probe: int64 values < 2^32 have zero high halves) ----
    const unsigned long long* p64 = (const unsigned long long*)edge_index_raw;
    const bool is64 = (((p64[0] | p64[1] | p64[2] | p64[3]) >> 32) == 0ULL);

    int src[EPT], dst[EPT];
#pragma unroll
    for (int k = 0; k < EPT; k++) {
        const long long e = blk_base + t + k * TPB;
        if (is64) {
            const long long* ei = (const long long*)edge_index_raw;
            src[k] = (int)ei[e];
            dst[k] = (int)ei[N_EDGES + e];
        } else {
            const int* ei = (const int*)edge_index_raw;
            src[k] = ei[e];
            dst[k] = ei[N_EDGES + e];
        }
        src[k] = min(N_NODES - 1, max(0, src[k]));
        dst[k] = min(N_NODES - 1, max(0, dst[k]));
    }

    // ---- pos gathers: single 16B load per node, both edges in flight ----
    float4 pd[EPT], ps[EPT];
#pragma unroll
    for (int k = 0; k < EPT; k++) {
        pd[k] = __ldg(&g_pos_pad[dst[k]]);
        ps[k] = __ldg(&g_pos_pad[src[k]]);
    }

    __syncthreads();   // s_shvec (shift) ready

    const float SQRT3 = 1.7320508075688772f;
    const float SQRT5 = 2.2360679774997896f;

#pragma unroll
    for (int k = 0; k < EPT; k++) {
        const int le = t + k * TPB;   // local edge index in block

        const float sx = s_shvec[le * 3 + 0];
        const float sy = s_shvec[le * 3 + 1];
        const float sz = s_shvec[le * 3 + 2];

        const float vx = pd[k].x - ps[k].x - sx;
        const float vy = pd[k].y - ps[k].y - sy;
        const float vz = pd[k].z - ps[k].z - sz;

        const float n2   = vx * vx + vy * vy + vz * vz;
        const float rinv = rsqrtf(n2);
        const float len  = n2 * rinv;

        const float x = vx * rinv;
        const float y = vy * rinv;
        const float z = vz * rinv;
        const float x2 = x * x, y2 = y * y, z2 = z * z;

        // in-place: same slots this thread just read
        s_shvec[le * 3 + 0] = vx;
        s_shvec[le * 3 + 1] = vy;
        s_shvec[le * 3 + 2] = vz;
        s_len[le] = len;

        s_sh[le * 9 + 0] = 1.0f;
        s_sh[le * 9 + 1] = SQRT3 * x;
        s_sh[le * 9 + 2] = SQRT3 * y;
        s_sh[le * 9 + 3] = SQRT3 * z;
        s_sh[le * 9 + 4] = SQRT5 * (SQRT3 * x * z);
        s_sh[le * 9 + 5] = SQRT5 * (SQRT3 * x * y);
        s_sh[le * 9 + 6] = SQRT5 * (y2 - 0.5f * (x2 + z2));
        s_sh[le * 9 + 7] = SQRT5 * (SQRT3 * y * z);
        s_sh[le * 9 + 8] = SQRT5 * (0.5f * SQRT3 * (z2 - x2));
    }

    __syncthreads();

    // ---- coalesced float4 stores ----
    // vec region: [0, 3E), block slice = 1536 floats = 384 float4
    {
        float4* gvec = (float4*)(out + blk_base * 3);
        const float4* svec = (const float4*)s_shvec;
        gvec[t] = svec[t];
        if (t < 384 - TPB) gvec[t + TPB] = svec[t + TPB];
    }
    // len region: [3E, 4E), block slice = 512 floats = 128 float4
    {
        float4* glen = (float4*)(out + 3LL * N_EDGES + blk_base);
        if (t < 128) glen[t] = ((const float4*)s_len)[t];
    }
    // sh region: [4E, 13E), block slice = 4608 floats = 1152 float4
    {
        float4* gsh = (float4*)(out + 4LL * N_EDGES + blk_base * 9);
        const float4* ssh = (const float4*)s_sh;
        gsh[t]       = ssh[t];
        gsh[t + 256] = ssh[t + 256];
        gsh[t + 512] = ssh[t + 512];
        gsh[t + 768] = ssh[t + 768];
        if (t < 128) gsh[t + 1024] = ssh[t + 1024];
    }
}

extern "C" void kernel_launch(void* const* d_in, const int* in_sizes, int n_in,
                              void* d_out, int out_size)
{
    // Identify inputs by element count (robust to metadata ordering):
    //   pos: 300000 floats, edge_index: 6400000 ints, shift: 9600000 floats
    const float* pos        = nullptr;
    const void*  edge_index = nullptr;
    const float* shift      = nullptr;

    for (int i = 0; i < n_in; i++) {
        if (in_sizes[i] == 3 * N_NODES)      pos        = (const float*)d_in[i];
        else if (in_sizes[i] == 2 * N_EDGES) edge_index = (const void*)d_in[i];
        else if (in_sizes[i] == 3 * N_EDGES) shift      = (const float*)d_in[i];
    }

    float* out = (float*)d_out;

    pos_pad_kernel<<<(N_NODES + 255) / 256, 256>>>(pos);

    const int blocks = N_EDGES / EPB;   // 6250, exact
    sh_edge_attrs_kernel<<<blocks, TPB>>>(edge_index, shift, out);
}

// round 6
// speedup vs baseline: 1.2536x; 1.2536x over previous
#include <cuda_runtime.h>
#include <cstdint>

#define N_EDGES 3200000
#define N_NODES 100000
#define TPB 256
#define NWARPS (TPB / 32)
// per-warp staging floats: vec 96 | len 32 | sh 288  = 416 floats (1664 B)
#define WBUF 416
#define W_VEC 0
#define W_LEN 96
#define W_SH  128

// 16B-aligned padded copy of pos: one LDG.128 per gather instead of 3 LDG.32.
__device__ float4 g_pos_pad[N_NODES];

__global__ __launch_bounds__(256)
void pos_pad_kernel(const float* __restrict__ pos)
{
    const int i = blockIdx.x * blockDim.x + threadIdx.x;
    if (i < N_NODES) {
        g_pos_pad[i] = make_float4(pos[i * 3 + 0], pos[i * 3 + 1], pos[i * 3 + 2], 0.0f);
    }
}

__global__ __launch_bounds__(256)
void sh_edge_attrs_kernel(const void* __restrict__ edge_index_raw,
                          const float* __restrict__ shift,
                          float* __restrict__ out)
{
    __shared__ float s_buf[NWARPS * WBUF];   // 13312 B

    const int t    = threadIdx.x;
    const int w    = t >> 5;
    const int lane = t & 31;

    float* wb = s_buf + w * WBUF;                       // this warp's slice
    const long long blk_base  = (long long)blockIdx.x * TPB;
    const long long warp_base = blk_base + (long long)w * 32;   // first edge of warp
    const long long e = warp_base + lane;

    // ---- edge indices first (get loads in flight) ----
    const unsigned long long* p64 = (const unsigned long long*)edge_index_raw;
    const bool is64 = (((p64[0] | p64[1] | p64[2] | p64[3]) >> 32) == 0ULL);

    int src, dst;
    if (is64) {
        const long long* ei = (const long long*)edge_index_raw;
        src = (int)ei[e];
        dst = (int)ei[N_EDGES + e];
    } else {
        const int* ei = (const int*)edge_index_raw;
        src = ei[e];
        dst = ei[N_EDGES + e];
    }
    src = min(N_NODES - 1, max(0, src));
    dst = min(N_NODES - 1, max(0, dst));

    // ---- stage this warp's shift slice: 24 float4, reusing vec slot ----
    {
        const float4* gshift = (const float4*)(shift + warp_base * 3);
        if (lane < 24) ((float4*)(wb + W_VEC))[lane] = gshift[lane];
    }

    // ---- pos gathers: single 16B load per node ----
    const float4 pd = __ldg(&g_pos_pad[dst]);
    const float4 ps = __ldg(&g_pos_pad[src]);

    __syncwarp();   // shift staged (warp-local)

    const float sx = wb[W_VEC + lane * 3 + 0];
    const float sy = wb[W_VEC + lane * 3 + 1];
    const float sz = wb[W_VEC + lane * 3 + 2];

    const float vx = pd.x - ps.x - sx;
    const float vy = pd.y - ps.y - sy;
    const float vz = pd.z - ps.z - sz;

    const float n2   = vx * vx + vy * vy + vz * vz;
    const float rinv = rsqrtf(n2);
    const float len  = n2 * rinv;

    const float x = vx * rinv;
    const float y = vy * rinv;
    const float z = vz * rinv;

    const float SQRT3 = 1.7320508075688772f;
    const float SQRT5 = 2.2360679774997896f;
    const float x2 = x * x, y2 = y * y, z2 = z * z;

    // in-place vec write (same slots this thread just read)
    wb[W_VEC + lane * 3 + 0] = vx;
    wb[W_VEC + lane * 3 + 1] = vy;
    wb[W_VEC + lane * 3 + 2] = vz;
    wb[W_LEN + lane] = len;

    float* shl = wb + W_SH + lane * 9;   // stride-9: conflict-free (gcd(9,32)=1)
    shl[0] = 1.0f;
    shl[1] = SQRT3 * x;
    shl[2] = SQRT3 * y;
    shl[3] = SQRT3 * z;
    shl[4] = SQRT5 * (SQRT3 * x * z);
    shl[5] = SQRT5 * (SQRT3 * x * y);
    shl[6] = SQRT5 * (y2 - 0.5f * (x2 + z2));
    shl[7] = SQRT5 * (SQRT3 * y * z);
    shl[8] = SQRT5 * (0.5f * SQRT3 * (z2 - x2));

    __syncwarp();   // warp results staged

    // ---- coalesced float4 copy-out, all warp-local ----
    // vec: 96 floats = 24 float4
    {
        float4* gvec = (float4*)(out + warp_base * 3);
        if (lane < 24) gvec[lane] = ((const float4*)(wb + W_VEC))[lane];
    }
    // len: 32 floats = 8 float4
    {
        float4* glen = (float4*)(out + 3LL * N_EDGES + warp_base);
        if (lane < 8) glen[lane] = ((const float4*)(wb + W_LEN))[lane];
    }
    // sh: 288 floats = 72 float4
    {
        float4* gsh = (float4*)(out + 4LL * N_EDGES + warp_base * 9);
        const float4* ssh = (const float4*)(wb + W_SH);
        gsh[lane]      = ssh[lane];
        gsh[lane + 32] = ssh[lane + 32];
        if (lane < 8) gsh[lane + 64] = ssh[lane + 64];
    }
}

extern "C" void kernel_launch(void* const* d_in, const int* in_sizes, int n_in,
                              void* d_out, int out_size)
{
    // Identify inputs by element count (robust to metadata ordering):
    //   pos: 300000 floats, edge_index: 6400000 ints, shift: 9600000 floats
    const float* pos        = nullptr;
    const void*  edge_index = nullptr;
    const float* shift      = nullptr;

    for (int i = 0; i < n_in; i++) {
        if (in_sizes[i] == 3 * N_NODES)      pos        = (const float*)d_in[i];
        else if (in_sizes[i] == 2 * N_EDGES) edge_index = (const void*)d_in[i];
        else if (in_sizes[i] == 3 * N_EDGES) shift      = (const float*)d_in[i];
    }

    float* out = (float*)d_out;

    pos_pad_kernel<<<(N_NODES + 255) / 256, 256>>>(pos);

    const int blocks = N_EDGES / TPB;   // 12500, exact
    sh_edge_attrs_kernel<<<blocks, TPB>>>(edge_index, shift, out);
}

// round 7
// speedup vs baseline: 1.3868x; 1.1063x over previous
#include <cuda_runtime.h>
#include <cstdint>

#define N_EDGES 3200000
#define N_NODES 100000
#define TPB 256

// 16B-aligned padded copy of pos: one LDG.128 per gather instead of 3 LDG.32.
__device__ float4 g_pos_pad[N_NODES];

__global__ __launch_bounds__(256)
void pos_pad_kernel(const float* __restrict__ pos)
{
    const int i = blockIdx.x * blockDim.x + threadIdx.x;
    if (i < N_NODES) {
        g_pos_pad[i] = make_float4(pos[i * 3 + 0], pos[i * 3 + 1], pos[i * 3 + 2], 0.0f);
    }
}

__global__ __launch_bounds__(256)
void sh_edge_attrs_kernel(const void* __restrict__ edge_index_raw,
                          const float* __restrict__ shift,
                          float* __restrict__ out)
{
    __shared__ alignas(16) float s_shift[TPB * 3];            // 3072 B
    __shared__ alignas(16) float s_vec[TPB * 3];              // 3072 B
    __shared__ alignas(16) float s_len[TPB];                  // 1024 B
    __shared__ alignas(16) float s_sh[TPB * 9];               // 9216 B
    __shared__ alignas(8)  unsigned long long s_mbar;

    const int t = threadIdx.x;
    const long long blk_base = (long long)blockIdx.x * TPB;

    const uint32_t mbar = (uint32_t)__cvta_generic_to_shared(&s_mbar);

    if (t == 0) {
        asm volatile("mbarrier.init.shared.b64 [%0], 1;" :: "r"(mbar) : "memory");
    }
    __syncthreads();

    // ---- async bulk load of this block's shift tile (bypasses L1 wavefronts) ----
    if (t == 0) {
        asm volatile("mbarrier.arrive.expect_tx.shared.b64 _, [%0], %1;"
                     :: "r"(mbar), "r"((unsigned)(TPB * 3 * 4)) : "memory");
        const uint32_t sdst = (uint32_t)__cvta_generic_to_shared(s_shift);
        asm volatile(
            "cp.async.bulk.shared::cta.global.mbarrier::complete_tx::bytes [%0], [%1], %2, [%3];"
            :: "r"(sdst), "l"(shift + blk_base * 3), "r"((unsigned)(TPB * 3 * 4)), "r"(mbar)
            : "memory");
    }

    // ---- edge indices (dtype probe: int64 values < 2^32 have zero high halves) ----
    const unsigned long long* p64 = (const unsigned long long*)edge_index_raw;
    const bool is64 = (((p64[0] | p64[1] | p64[2] | p64[3]) >> 32) == 0ULL);

    const long long e = blk_base + t;
    int src, dst;
    if (is64) {
        const long long* ei = (const long long*)edge_index_raw;
        src = (int)ei[e];
        dst = (int)ei[N_EDGES + e];
    } else {
        const int* ei = (const int*)edge_index_raw;
        src = ei[e];
        dst = ei[N_EDGES + e];
    }
    src = min(N_NODES - 1, max(0, src));
    dst = min(N_NODES - 1, max(0, dst));

    // ---- pos gathers: single 16B load per node, in flight during the bulk load ----
    const float4 pd = __ldg(&g_pos_pad[dst]);
    const float4 ps = __ldg(&g_pos_pad[src]);

    // ---- wait for shift tile ----
    {
        uint32_t done;
        asm volatile(
            "{\n\t"
            ".reg .pred p;\n\t"
            "mbarrier.try_wait.parity.acquire.cta.shared::cta.b64 p, [%1], 0;\n\t"
            "selp.b32 %0, 1, 0, p;\n\t"
            "}"
            : "=r"(done) : "r"(mbar) : "memory");
        if (!done) {
            asm volatile(
                "{\n\t"
                ".reg .pred P1;\n\t"
                "WAIT_LOOP_%=:\n\t"
                "mbarrier.try_wait.parity.acquire.cta.shared::cta.b64 P1, [%0], 0, 0x989680;\n\t"
                "@P1 bra.uni WAIT_DONE_%=;\n\t"
                "bra.uni WAIT_LOOP_%=;\n\t"
                "WAIT_DONE_%=:\n\t"
                "}"
                :: "r"(mbar) : "memory");
        }
    }

    const float sx = s_shift[t * 3 + 0];
    const float sy = s_shift[t * 3 + 1];
    const float sz = s_shift[t * 3 + 2];

    const float vx = pd.x - ps.x - sx;
    const float vy = pd.y - ps.y - sy;
    const float vz = pd.z - ps.z - sz;

    const float n2   = vx * vx + vy * vy + vz * vz;
    const float rinv = rsqrtf(n2);
    const float len  = n2 * rinv;

    const float x = vx * rinv;
    const float y = vy * rinv;
    const float z = vz * rinv;

    const float SQRT3 = 1.7320508075688772f;
    const float SQRT5 = 2.2360679774997896f;
    const float x2 = x * x, y2 = y * y, z2 = z * z;

    // ---- stage results (odd strides -> bank-conflict-free) ----
    s_vec[t * 3 + 0] = vx;
    s_vec[t * 3 + 1] = vy;
    s_vec[t * 3 + 2] = vz;
    s_len[t] = len;

    float* shl = s_sh + t * 9;
    shl[0] = 1.0f;
    shl[1] = SQRT3 * x;
    shl[2] = SQRT3 * y;
    shl[3] = SQRT3 * z;
    shl[4] = SQRT5 * (SQRT3 * x * z);
    shl[5] = SQRT5 * (SQRT3 * x * y);
    shl[6] = SQRT5 * (y2 - 0.5f * (x2 + z2));
    shl[7] = SQRT5 * (SQRT3 * y * z);
    shl[8] = SQRT5 * (0.5f * SQRT3 * (z2 - x2));

    __syncthreads();

    // ---- async bulk stores: TMA reads smem directly, no L1 wavefronts ----
    if (t == 0) {
        asm volatile("fence.proxy.async.shared::cta;" ::: "memory");

        const uint32_t svec = (uint32_t)__cvta_generic_to_shared(s_vec);
        const uint32_t slen = (uint32_t)__cvta_generic_to_shared(s_len);
        const uint32_t ssh  = (uint32_t)__cvta_generic_to_shared(s_sh);

        float* gvec = out + blk_base * 3;
        float* glen = out + 3LL * N_EDGES + blk_base;
        float* gsh  = out + 4LL * N_EDGES + blk_base * 9;

        asm volatile("cp.async.bulk.global.shared::cta.bulk_group [%0], [%1], %2;"
                     :: "l"(gvec), "r"(svec), "r"((unsigned)(TPB * 3 * 4)) : "memory");
        asm volatile("cp.async.bulk.global.shared::cta.bulk_group [%0], [%1], %2;"
                     :: "l"(glen), "r"(slen), "r"((unsigned)(TPB * 4)) : "memory");
        asm volatile("cp.async.bulk.global.shared::cta.bulk_group [%0], [%1], %2;"
                     :: "l"(gsh), "r"(ssh), "r"((unsigned)(TPB * 9 * 4)) : "memory");
        asm volatile("cp.async.bulk.commit_group;" ::: "memory");
        asm volatile("cp.async.bulk.wait_group 0;" ::: "memory");
    }
}

extern "C" void kernel_launch(void* const* d_in, const int* in_sizes, int n_in,
                              void* d_out, int out_size)
{
    // Identify inputs by element count (robust to metadata ordering):
    //   pos: 300000 floats, edge_index: 6400000 ints, shift: 9600000 floats
    const float* pos        = nullptr;
    const void*  edge_index = nullptr;
    const float* shift      = nullptr;

    for (int i = 0; i < n_in; i++) {
        if (in_sizes[i] == 3 * N_NODES)      pos        = (const float*)d_in[i];
        else if (in_sizes[i] == 2 * N_EDGES) edge_index = (const void*)d_in[i];
        else if (in_sizes[i] == 3 * N_EDGES) shift      = (const float*)d_in[i];
    }

    float* out = (float*)d_out;

    pos_pad_kernel<<<(N_NODES + 255) / 256, 256>>>(pos);

    const int blocks = N_EDGES / TPB;   // 12500, exact
    sh_edge_attrs_kernel<<<blocks, TPB>>>(edge_index, shift, out);
}